// round 11
// baseline (speedup 1.0000x reference)
#include <cuda_runtime.h>

#define Bb   4
#define Nn   4096
#define Cc   512
#define Kk   20
#define HIDD 64
#define ROWS (Bb*Nn)          // 16384
#define BNK_INV (1.0f/327680.0f)
#define BN_INV  (1.0f/16384.0f)
#define EPSV 1e-5f
#define SLOPE 0.2f
#define FULLM 0xffffffffu

typedef unsigned long long ull;
__device__ __forceinline__ ull pk2(float lo, float hi) {
    ull r; asm("mov.b64 %0,{%1,%2};" : "=l"(r) : "f"(lo), "f"(hi)); return r;
}
__device__ __forceinline__ void fma2(ull& d, ull a, ull b) {
    asm("fma.rn.f32x2 %0, %1, %2, %0;" : "+l"(d) : "l"(a), "l"(b));
}
__device__ __forceinline__ ull fma2g(ull a, ull b, ull c) {
    ull r; asm("fma.rn.f32x2 %0, %1, %2, %3;" : "=l"(r) : "l"(a), "l"(b), "l"(c)); return r;
}
__device__ __forceinline__ ull mul2(ull a, ull b) {
    ull r; asm("mul.rn.f32x2 %0, %1, %2;" : "=l"(r) : "l"(a), "l"(b)); return r;
}
__device__ __forceinline__ ull add2(ull a, ull b) {
    ull r; asm("add.rn.f32x2 %0, %1, %2;" : "=l"(r) : "l"(a), "l"(b)); return r;
}
__device__ __forceinline__ float2 up2(ull v) {
    float lo, hi; asm("mov.b64 {%0,%1},%2;" : "=f"(lo), "=f"(hi) : "l"(v));
    return make_float2(lo, hi);
}

// ---------------- scratch ----------------
__device__ float  g_p   [ROWS*HIDD];
__device__ float  g_q   [ROWS*HIDD];
__device__ int    g_idx [ROWS*Kk];
__device__ float4 g_xyz4[ROWS];
__device__ float  g_hmax[ROWS*HIDD];
__device__ float  g_hmin[ROWS*HIDD];
__device__ float  g_hn  [ROWS*HIDD];
__device__ float  g_sum [HIDD];
__device__ float  g_sumsq[HIDD];
__device__ float  g_af  [HIDD];
__device__ float  g_cf  [HIDD];
__device__ float  g_mv  [HIDD];
__device__ float  g_MM  [HIDD*HIDD];
__device__ float  g_a2  [Cc];
__device__ float  g_c2  [Cc];
__device__ float  g_wT1 [Cc*128];
__device__ float  g_w2T [HIDD*Cc];
__device__ unsigned int g_cnt;

// ---------------- K0a: pack xyz + zero accumulators (feeds knn immediately) ----------------
__global__ void pack_zero_kernel(const float* __restrict__ xyz) {
    int i = blockIdx.x*256 + threadIdx.x;
    if (i == 0) g_cnt = 0u;
    if (i < HIDD) { g_sum[i] = 0.f; g_sumsq[i] = 0.f; g_mv[i] = 0.f; }
    if (i < HIDD*HIDD) g_MM[i] = 0.f;
    if (i < ROWS) {
        float x = xyz[i*3+0], y = xyz[i*3+1], z = xyz[i*3+2];
        g_xyz4[i] = make_float4(x, y, z, x*x + y*y + z*z);
    }
}

// ---------------- K0b: weight prep (feeds gemm_pq / gemm_out) ----------------
__global__ void wprep_kernel(const float* __restrict__ w1, const float* __restrict__ w2) {
    int i = blockIdx.x*256 + threadIdx.x;
    if (i < Cc*128) {
        int c = i >> 7, j = i & 127;
        float v;
        if (j < 64) v = w1[j*(2*Cc) + c];
        else { int d = j - 64; v = w1[d*(2*Cc) + Cc + c] - w1[d*(2*Cc) + c]; }
        g_wT1[i] = v;
    } else {
        int t = i - Cc*128;
        if (t < HIDD*Cc) {
            int d = t >> 9, e = t & 511;
            g_w2T[t] = w2[e*HIDD + d];
        }
    }
}

// ---------------- K1: KNN ----------------
__device__ __forceinline__ void insert_cand(float& dist, int& idx, float& thr,
                                            float dn, int in, int lane) {
    int pos = __popc(__ballot_sync(FULLM, dist <= dn));
    float sd = __shfl_up_sync(FULLM, dist, 1);
    int   si = __shfl_up_sync(FULLM, idx, 1);
    if (lane == pos)      { dist = dn; idx = in; }
    else if (lane > pos)  { dist = sd; idx = si; }
    thr = __shfl_sync(FULLM, dist, Kk - 1);
}

#define KTILE 1024
__global__ void __launch_bounds__(256) knn_kernel() {
    __shared__ float4 sa[KTILE/2];   // (x0,x1,y0,y1) per pair
    __shared__ float4 sb[KTILE/2];   // (z0,z1,w0,w1) per pair
    const int lane = threadIdx.x & 31;
    const int warp = threadIdx.x >> 5;
    const int qrow = blockIdx.x * 8 + warp;
    const int b = qrow >> 12;
    const float4* xb4 = g_xyz4 + (b << 12);
    const float4 qv = g_xyz4[qrow];
    const ull qx2 = pk2(qv.x, qv.x), qy2 = pk2(qv.y, qv.y);
    const ull qz2 = pk2(qv.z, qv.z), qw2 = pk2(qv.w, qv.w);
    const ull m2  = pk2(-2.0f, -2.0f);
    const float INF = __int_as_float(0x7f800000);

    float dist; int idx;
    {
        float4 c = xb4[lane];
        float dot = fmaf(qv.x, c.x, fmaf(qv.y, c.y, qv.z * c.z));
        dist = fmaf(-2.0f, dot, qv.w + c.w);
        idx = lane;
#pragma unroll
        for (int k = 2; k <= 32; k <<= 1) {
#pragma unroll
            for (int j = k >> 1; j > 0; j >>= 1) {
                float od = __shfl_xor_sync(FULLM, dist, j);
                int   oi = __shfl_xor_sync(FULLM, idx,  j);
                bool lowLane   = (lane & j) == 0;
                bool asc       = (lane & k) == 0;
                bool keepSmall = (lowLane == asc);
                bool otherSmall = (od < dist) | ((od == dist) & (oi < idx));
                if (otherSmall == keepSmall) { dist = od; idx = oi; }
            }
        }
    }
    float thr = __shfl_sync(FULLM, dist, Kk - 1);

    for (int t0 = 0; t0 < Nn; t0 += KTILE) {
        __syncthreads();
        for (int j = threadIdx.x; j < KTILE/2; j += 256) {
            float4 c0 = xb4[t0 + 2*j], c1 = xb4[t0 + 2*j + 1];
            sa[j] = make_float4(c0.x, c1.x, c0.y, c1.y);
            sb[j] = make_float4(c0.z, c1.z, c0.w, c1.w);
        }
        __syncthreads();
        const bool firstTile = (t0 == 0);
#pragma unroll 2
        for (int pb = 0; pb < KTILE/2; pb += 32) {
            float4 A  = sa[pb + lane];
            float4 Bv = sb[pb + lane];
            ull cx2 = pk2(A.x, A.y), cy2 = pk2(A.z, A.w);
            ull cz2 = pk2(Bv.x, Bv.y), cw2 = pk2(Bv.z, Bv.w);
            ull dot2 = fma2g(qx2, cx2, fma2g(qy2, cy2, mul2(qz2, cz2)));
            ull d2 = fma2g(m2, dot2, add2(qw2, cw2));
            float2 dd = up2(d2);
            if (firstTile && pb == 0 && lane < 16) { dd.x = INF; dd.y = INF; }
            unsigned m = __ballot_sync(FULLM, (dd.x < thr) | (dd.y < thr));
            while (m) {
                int src = __ffs(m) - 1; m &= m - 1;
                float d0 = __shfl_sync(FULLM, dd.x, src);
                float d1 = __shfl_sync(FULLM, dd.y, src);
                int ibase = t0 + (pb + src) * 2;
                if (d0 < thr) insert_cand(dist, idx, thr, d0, ibase,     lane);
                if (d1 < thr) insert_cand(dist, idx, thr, d1, ibase + 1, lane);
            }
        }
    }
    if (lane < Kk) g_idx[qrow*Kk + lane] = idx;
}

// ---------------- K2: SGEMM [16384x512]x[512x128] -> p|q ----------------
// 128x128 tile, 256 threads, TM=TN=8, KT=32 double-buffered (compute 1024cyc > 600cyc DRAM)
#define PQ_ASZ (32*132)
#define PQ_BSZ (32*136)
#define PQ_SMEM ((2*PQ_ASZ + 2*PQ_BSZ)*4)
__global__ void __launch_bounds__(256) gemm_pq_kernel(const float* __restrict__ X) {
    extern __shared__ float smem[];
    float* AsB[2] = { smem, smem + PQ_ASZ };
    float* BsB[2] = { smem + 2*PQ_ASZ, smem + 2*PQ_ASZ + PQ_BSZ };
    const int tid = threadIdx.x;
    const int r0 = blockIdx.x * 128;
    const int ty = tid >> 4;            // 0..15
    const int tx = tid & 15;            // 0..15
    ull acc[8][4];
#pragma unroll
    for (int i = 0; i < 8; ++i)
#pragma unroll
        for (int j = 0; j < 4; ++j) acc[i][j] = 0ull;

    const int aRow = tid >> 1;          // 0..127
    const int aCol = (tid & 1) << 4;    // 0 or 16
    const int bRow = (tid >> 4) << 1;   // 0,2,..,30
    const int bCol = (tid & 15) << 3;   // 0..120
    const float* aPtr = &X[(r0 + aRow)*Cc + aCol];
    const float* bPtr = &g_wT1[bRow*128 + bCol];

    float4 ra[4], rb[4];
#pragma unroll
    for (int c = 0; c < 4; ++c) ra[c] = *(const float4*)(aPtr + 4*c);
    rb[0] = *(const float4*)(bPtr);
    rb[1] = *(const float4*)(bPtr + 4);
    rb[2] = *(const float4*)(bPtr + 128);
    rb[3] = *(const float4*)(bPtr + 132);
    {
        float* as = AsB[0];
#pragma unroll
        for (int c = 0; c < 4; ++c) {
            as[(aCol+4*c+0)*132+aRow]=ra[c].x; as[(aCol+4*c+1)*132+aRow]=ra[c].y;
            as[(aCol+4*c+2)*132+aRow]=ra[c].z; as[(aCol+4*c+3)*132+aRow]=ra[c].w;
        }
        float4* b0 = (float4*)&BsB[0][bRow*136 + bCol];
        b0[0] = rb[0]; b0[1] = rb[1];
        float4* b1 = (float4*)&BsB[0][(bRow+1)*136 + bCol];
        b1[0] = rb[2]; b1[1] = rb[3];
    }
    __syncthreads();

    int buf = 0;
    for (int kt = 0; kt < Cc; kt += 32) {
        const bool more = (kt + 32) < Cc;
        if (more) {
#pragma unroll
            for (int c = 0; c < 4; ++c) ra[c] = *(const float4*)(aPtr + kt + 32 + 4*c);
            rb[0] = *(const float4*)(bPtr + (kt+32)*128);
            rb[1] = *(const float4*)(bPtr + (kt+32)*128 + 4);
            rb[2] = *(const float4*)(bPtr + (kt+33)*128);
            rb[3] = *(const float4*)(bPtr + (kt+33)*128 + 4);
        }
        const float* as = AsB[buf];
        const float* bs = BsB[buf];
#pragma unroll
        for (int kk = 0; kk < 32; ++kk) {
            float4 av0 = *(const float4*)&as[kk*132 + ty*8];
            float4 av1 = *(const float4*)&as[kk*132 + ty*8 + 4];
            float4 bv0 = *(const float4*)&bs[kk*136 + tx*8];
            float4 bv1 = *(const float4*)&bs[kk*136 + tx*8 + 4];
            ull b0 = pk2(bv0.x, bv0.y), b1 = pk2(bv0.z, bv0.w);
            ull b2p = pk2(bv1.x, bv1.y), b3 = pk2(bv1.z, bv1.w);
            float rav[8] = {av0.x,av0.y,av0.z,av0.w,av1.x,av1.y,av1.z,av1.w};
#pragma unroll
            for (int i = 0; i < 8; ++i) {
                ull ap = pk2(rav[i], rav[i]);
                fma2(acc[i][0], ap, b0);  fma2(acc[i][1], ap, b1);
                fma2(acc[i][2], ap, b2p); fma2(acc[i][3], ap, b3);
            }
        }
        if (more) {
            float* asn = AsB[buf^1];
#pragma unroll
            for (int c = 0; c < 4; ++c) {
                asn[(aCol+4*c+0)*132+aRow]=ra[c].x; asn[(aCol+4*c+1)*132+aRow]=ra[c].y;
                asn[(aCol+4*c+2)*132+aRow]=ra[c].z; asn[(aCol+4*c+3)*132+aRow]=ra[c].w;
            }
            float4* b0 = (float4*)&BsB[buf^1][bRow*136 + bCol];
            b0[0] = rb[0]; b0[1] = rb[1];
            float4* b1 = (float4*)&BsB[buf^1][(bRow+1)*136 + bCol];
            b1[0] = rb[2]; b1[1] = rb[3];
            __syncthreads();
        }
        buf ^= 1;
    }
#pragma unroll
    for (int i = 0; i < 8; ++i) {
        int row = r0 + ty*8 + i;
        float2 v0 = up2(acc[i][0]), v1 = up2(acc[i][1]);
        float2 v2 = up2(acc[i][2]), v3 = up2(acc[i][3]);
        float4 lo = make_float4(v0.x, v0.y, v1.x, v1.y);
        float4 hi = make_float4(v2.x, v2.y, v3.x, v3.y);
        if (tx < 8) {
            float4* dst = (float4*)&g_p[row*64 + tx*8];
            dst[0] = lo; dst[1] = hi;
        } else {
            float4* dst = (float4*)&g_q[row*64 + (tx-8)*8];
            dst[0] = lo; dst[1] = hi;
        }
    }
}

// ---------------- K3: gather + per-(b,n) max/min + global stats + last-block finalize1 ----------------
#define GATHER_GRID (ROWS/4)
__global__ void __launch_bounds__(256) gather_stats_kernel(const float* __restrict__ g1,
                                                           const float* __restrict__ b1) {
    __shared__ int sidx[4][Kk];
    __shared__ float rs[256], rs2[256];
    __shared__ bool isLast;
    const int tid = threadIdx.x;
    const int w = tid >> 6;
    const int d = tid & 63;
    const int r = blockIdx.x*4 + w;
    if (d < Kk) sidx[w][d] = g_idx[r*Kk + d];
    __syncthreads();
    const int b = r >> 12;
    const float* pb = g_p + (b << 12)*HIDD;
    const float qvv = g_q[r*HIDD + d];
    float mx = __int_as_float(0xff800000);
    float mn = __int_as_float(0x7f800000);
    float s = 0.f, s2 = 0.f;
#pragma unroll
    for (int k = 0; k < Kk; ++k) {
        float pv = pb[sidx[w][k]*HIDD + d];
        float h = pv + qvv;
        mx = fmaxf(mx, h); mn = fminf(mn, h);
        s += h; s2 = fmaf(h, h, s2);
    }
    g_hmax[r*HIDD + d] = mx;
    g_hmin[r*HIDD + d] = mn;
    rs[tid] = s; rs2[tid] = s2;
    __syncthreads();
    if (tid < 64) {
        float a  = rs[tid]  + rs[tid+64]  + rs[tid+128]  + rs[tid+192];
        float a2 = rs2[tid] + rs2[tid+64] + rs2[tid+128] + rs2[tid+192];
        atomicAdd(&g_sum[tid],   a);
        atomicAdd(&g_sumsq[tid], a2);
    }
    __threadfence();
    __syncthreads();
    if (tid == 0) {
        unsigned v = atomicInc(&g_cnt, 0xffffffffu);
        isLast = (v == GATHER_GRID - 1);
    }
    __syncthreads();
    if (isLast && tid < 64) {
        float su  = __ldcg(&g_sum[tid]);
        float sq  = __ldcg(&g_sumsq[tid]);
        float mu  = su * BNK_INV;
        float var = sq * BNK_INV - mu*mu;
        if (var < 0.f) var = 0.f;
        float a = g1[tid] * rsqrtf(var + EPSV);
        g_af[tid] = a;
        g_cf[tid] = b1[tid] - mu*a;
    }
}

// ---------------- K5: hn = lrelu(a*hsel + c), accumulate m and M (128 blocks) ----------------
__global__ void __launch_bounds__(256) hn_moments_kernel() {
    __shared__ float sh[64][68];
    __shared__ float sa[64], sc2[64];
    const int tid = threadIdx.x;
    if (tid < 64) { sa[tid] = g_af[tid]; sc2[tid] = g_cf[tid]; }
    const int du = (tid >> 4) << 2;
    const int dv = (tid & 15) << 2;
    float acc[4][4];
#pragma unroll
    for (int i = 0; i < 4; ++i)
#pragma unroll
        for (int j = 0; j < 4; ++j) acc[i][j] = 0.f;
    float msum = 0.f;

    for (int pass = 0; pass < 2; ++pass) {
        __syncthreads();
        const int r0 = blockIdx.x*128 + pass*64;
        for (int t = tid; t < 64*64; t += 256) {
            int rr = t >> 6, d = t & 63;
            float a = sa[d], c = sc2[d];
            float hv = (a >= 0.f) ? g_hmax[(r0+rr)*HIDD + d] : g_hmin[(r0+rr)*HIDD + d];
            float z = fmaf(a, hv, c);
            z = (z >= 0.f) ? z : SLOPE*z;
            sh[rr][d] = z;
            g_hn[(r0+rr)*HIDD + d] = z;
        }
        __syncthreads();
        if (tid < 64) {
            float s = 0.f;
#pragma unroll
            for (int rr = 0; rr < 64; ++rr) s += sh[rr][tid];
            msum += s;
        }
#pragma unroll 4
        for (int rr = 0; rr < 64; ++rr) {
            float4 u = *(const float4*)&sh[rr][du];
            float4 v = *(const float4*)&sh[rr][dv];
            float uu[4] = {u.x,u.y,u.z,u.w};
            float vv[4] = {v.x,v.y,v.z,v.w};
#pragma unroll
            for (int i = 0; i < 4; ++i)
#pragma unroll
                for (int j = 0; j < 4; ++j) acc[i][j] = fmaf(uu[i], vv[j], acc[i][j]);
        }
    }
    if (tid < 64) atomicAdd(&g_mv[tid], msum);
#pragma unroll
    for (int i = 0; i < 4; ++i)
#pragma unroll
        for (int j = 0; j < 4; ++j)
            atomicAdd(&g_MM[(du+i)*64 + dv+j], acc[i][j]);
}

// ---------------- K6: one warp per output channel e: v = w2_e*M, then a2/c2 ----------------
__global__ void __launch_bounds__(256) mmv_fin2_kernel(const float* __restrict__ w2,
                                                       const float* __restrict__ g2,
                                                       const float* __restrict__ b2) {
    const int gwarp = (blockIdx.x*256 + threadIdx.x) >> 5;   // 0..511 = e
    const int lane = threadIdx.x & 31;
    const int e = gwarp;
    const float* w2e = w2 + e*64;
    float vv0 = 0.f, vv1 = 0.f;
#pragma unroll
    for (int d = 0; d < 64; ++d) {
        float w = w2e[d];
        vv0 = fmaf(w, g_MM[d*64 + lane],      vv0);
        vv1 = fmaf(w, g_MM[d*64 + lane + 32], vv1);
    }
    float wl0 = w2e[lane], wl1 = w2e[lane + 32];
    float ey = fmaf(wl0, vv0, wl1*vv1);
    float mu = fmaf(wl0, g_mv[lane], wl1*g_mv[lane+32]);
#pragma unroll
    for (int off = 16; off > 0; off >>= 1) {
        ey += __shfl_down_sync(FULLM, ey, off);
        mu += __shfl_down_sync(FULLM, mu, off);
    }
    if (lane == 0) {
        mu *= BN_INV;
        ey *= BN_INV;
        float var = ey - mu*mu;
        if (var < 0.f) var = 0.f;
        float a = g2[e]*rsqrtf(var + EPSV);
        g_a2[e] = a;
        g_c2[e] = b2[e] - mu*a;
    }
}

// ---------------- K7: out = lrelu(a2 * (hn @ w2T) + c2), double-buffered ----------------
#define O_ASZ (16*132)
#define O_BSZ (16*136)
__global__ void __launch_bounds__(256) gemm_out_kernel(float* __restrict__ out) {
    __shared__ float As[2][O_ASZ];
    __shared__ float Bs[2][O_BSZ];
    const int tid = threadIdx.x;
    const int r0 = blockIdx.x * 128;
    const int e0 = blockIdx.y * 128;
    const int tx = tid & 15, ty = tid >> 4;
    ull acc[8][4];
#pragma unroll
    for (int i = 0; i < 8; ++i)
#pragma unroll
        for (int j = 0; j < 4; ++j) acc[i][j] = 0ull;

    const int aRow = tid >> 1;          // 0..127
    const int aCol = (tid & 1) << 3;    // 0 or 8
    const int bRow = tid >> 4;          // 0..15
    const int bCol = (tid & 15) << 3;   // 0..120
    const float* aPtr = &g_hn[(r0 + aRow)*HIDD + aCol];
    const float* bPtr = &g_w2T[bRow*Cc + e0 + bCol];

    float4 ra0 = *(const float4*)(aPtr);
    float4 ra1 = *(const float4*)(aPtr + 4);
    float4 rb0 = *(const float4*)(bPtr);
    float4 rb1 = *(const float4*)(bPtr + 4);
    {
        float* as = As[0];
        as[(aCol+0)*132+aRow]=ra0.x; as[(aCol+1)*132+aRow]=ra0.y;
        as[(aCol+2)*132+aRow]=ra0.z; as[(aCol+3)*132+aRow]=ra0.w;
        as[(aCol+4)*132+aRow]=ra1.x; as[(aCol+5)*132+aRow]=ra1.y;
        as[(aCol+6)*132+aRow]=ra1.z; as[(aCol+7)*132+aRow]=ra1.w;
        float4* bsv = (float4*)&Bs[0][bRow*136 + bCol];
        bsv[0] = rb0; bsv[1] = rb1;
    }
    __syncthreads();

    int buf = 0;
    for (int kt = 0; kt < HIDD; kt += 16) {
        const bool more = (kt + 16) < HIDD;
        if (more) {
            ra0 = *(const float4*)(aPtr + kt + 16);
            ra1 = *(const float4*)(aPtr + kt + 20);
            rb0 = *(const float4*)(bPtr + (kt+16)*Cc);
            rb1 = *(const float4*)(bPtr + (kt+16)*Cc + 4);
        }
        const float* as = As[buf];
        const float* bs = Bs[buf];
#pragma unroll
        for (int kk = 0; kk < 16; ++kk) {
            float4 av0 = *(const float4*)&as[kk*132 + ty*8];
            float4 av1 = *(const float4*)&as[kk*132 + ty*8 + 4];
            float4 bv0 = *(const float4*)&bs[kk*136 + tx*8];
            float4 bv1 = *(const float4*)&bs[kk*136 + tx*8 + 4];
            ull b0 = pk2(bv0.x, bv0.y), b1 = pk2(bv0.z, bv0.w);
            ull b2p = pk2(bv1.x, bv1.y), b3 = pk2(bv1.z, bv1.w);
            float rav[8] = {av0.x,av0.y,av0.z,av0.w,av1.x,av1.y,av1.z,av1.w};
#pragma unroll
            for (int i = 0; i < 8; ++i) {
                ull ap = pk2(rav[i], rav[i]);
                fma2(acc[i][0], ap, b0); fma2(acc[i][1], ap, b1);
                fma2(acc[i][2], ap, b2p); fma2(acc[i][3], ap, b3);
            }
        }
        if (more) {
            float* asn = As[buf^1];
            asn[(aCol+0)*132+aRow]=ra0.x; asn[(aCol+1)*132+aRow]=ra0.y;
            asn[(aCol+2)*132+aRow]=ra0.z; asn[(aCol+3)*132+aRow]=ra0.w;
            asn[(aCol+4)*132+aRow]=ra1.x; asn[(aCol+5)*132+aRow]=ra1.y;
            asn[(aCol+6)*132+aRow]=ra1.z; asn[(aCol+7)*132+aRow]=ra1.w;
            float4* bsn = (float4*)&Bs[buf^1][bRow*136 + bCol];
            bsn[0] = rb0; bsn[1] = rb1;
            __syncthreads();
        }
        buf ^= 1;
    }
    float a2r[8], c2r[8];
#pragma unroll
    for (int j = 0; j < 8; ++j) {
        a2r[j] = g_a2[e0 + tx*8 + j];
        c2r[j] = g_c2[e0 + tx*8 + j];
    }
#pragma unroll
    for (int i = 0; i < 8; ++i) {
        int row = r0 + ty*8 + i;
        float av[8];
        float2 t0v = up2(acc[i][0]); av[0]=t0v.x; av[1]=t0v.y;
        float2 t1v = up2(acc[i][1]); av[2]=t1v.x; av[3]=t1v.y;
        float2 t2v = up2(acc[i][2]); av[4]=t2v.x; av[5]=t2v.y;
        float2 t3v = up2(acc[i][3]); av[6]=t3v.x; av[7]=t3v.y;
        float v[8];
#pragma unroll
        for (int j = 0; j < 8; ++j) {
            float z = fmaf(a2r[j], av[j], c2r[j]);
            v[j] = (z >= 0.f) ? z : SLOPE*z;
        }
        float4* dst = (float4*)&out[row*Cc + e0 + tx*8];
        dst[0] = make_float4(v[0], v[1], v[2], v[3]);
        dst[1] = make_float4(v[4], v[5], v[6], v[7]);
    }
}

// ---------------- stream/event singletons ----------------
struct SideStream {
    cudaStream_t s;
    cudaEvent_t  forkEv, joinEv;
    SideStream() {
        cudaStreamCreateWithFlags(&s, cudaStreamNonBlocking);
        cudaEventCreateWithFlags(&forkEv, cudaEventDisableTiming);
        cudaEventCreateWithFlags(&joinEv, cudaEventDisableTiming);
        cudaFuncSetAttribute(gemm_pq_kernel,
                             cudaFuncAttributeMaxDynamicSharedMemorySize, PQ_SMEM);
    }
};
static SideStream& side() { static SideStream ss; return ss; }

// ---------------- launch ----------------
extern "C" void kernel_launch(void* const* d_in, const int* in_sizes, int n_in,
                              void* d_out, int out_size) {
    const float* x   = (const float*)d_in[0];
    const float* xyz = (const float*)d_in[1];
    const float* w1  = (const float*)d_in[2];
    const float* g1  = (const float*)d_in[3];
    const float* b1  = (const float*)d_in[4];
    const float* w2  = (const float*)d_in[5];
    const float* g2  = (const float*)d_in[6];
    const float* b2  = (const float*)d_in[7];
    float* out = (float*)d_out;
    SideStream& ss = side();

    // stream 0: pack/zero -> fork
    pack_zero_kernel<<<64, 256>>>(xyz);
    cudaEventRecord(ss.forkEv, 0);
    cudaStreamWaitEvent(ss.s, ss.forkEv, 0);

    // side stream: KNN (ALU/issue-bound) || main stream: weights + GEMM (fma/smem-bound)
    knn_kernel<<<2048, 256, 0, ss.s>>>();
    cudaEventRecord(ss.joinEv, ss.s);

    wprep_kernel<<<384, 256>>>(w1, w2);
    gemm_pq_kernel<<<128, 256, PQ_SMEM>>>(x);

    // join: gather needs both knn idx and p|q
    cudaStreamWaitEvent(0, ss.joinEv, 0);
    gather_stats_kernel<<<GATHER_GRID, 256>>>(g1, b1);
    hn_moments_kernel<<<128, 256>>>();
    mmv_fin2_kernel<<<64, 256>>>(w2, g2, b2);
    gemm_out_kernel<<<dim3(ROWS/128, Cc/128), 256>>>(out);
}

// round 12
// speedup vs baseline: 1.1047x; 1.1047x over previous
#include <cuda_runtime.h>

#define Bb   4
#define Nn   4096
#define Cc   512
#define Kk   20
#define HIDD 64
#define ROWS (Bb*Nn)          // 16384
#define BNK_INV (1.0f/327680.0f)
#define BN_INV  (1.0f/16384.0f)
#define EPSV 1e-5f
#define SLOPE 0.2f
#define FULLM 0xffffffffu

typedef unsigned long long ull;
__device__ __forceinline__ ull pk2(float lo, float hi) {
    ull r; asm("mov.b64 %0,{%1,%2};" : "=l"(r) : "f"(lo), "f"(hi)); return r;
}
__device__ __forceinline__ void fma2(ull& d, ull a, ull b) {
    asm("fma.rn.f32x2 %0, %1, %2, %0;" : "+l"(d) : "l"(a), "l"(b));
}
__device__ __forceinline__ ull fma2g(ull a, ull b, ull c) {
    ull r; asm("fma.rn.f32x2 %0, %1, %2, %3;" : "=l"(r) : "l"(a), "l"(b), "l"(c)); return r;
}
__device__ __forceinline__ ull mul2(ull a, ull b) {
    ull r; asm("mul.rn.f32x2 %0, %1, %2;" : "=l"(r) : "l"(a), "l"(b)); return r;
}
__device__ __forceinline__ ull add2(ull a, ull b) {
    ull r; asm("add.rn.f32x2 %0, %1, %2;" : "=l"(r) : "l"(a), "l"(b)); return r;
}
__device__ __forceinline__ float2 up2(ull v) {
    float lo, hi; asm("mov.b64 {%0,%1},%2;" : "=f"(lo), "=f"(hi) : "l"(v));
    return make_float2(lo, hi);
}

// ---------------- scratch ----------------
__device__ float  g_p   [ROWS*HIDD];
__device__ float  g_q   [ROWS*HIDD];
__device__ int    g_idx [ROWS*Kk];
__device__ float4 g_xyz4[ROWS];
__device__ float  g_hmax[ROWS*HIDD];
__device__ float  g_hmin[ROWS*HIDD];
__device__ float  g_hn  [ROWS*HIDD];
__device__ float  g_sum [HIDD];
__device__ float  g_sumsq[HIDD];
__device__ float  g_af  [HIDD];
__device__ float  g_cf  [HIDD];
__device__ float  g_mv  [HIDD];
__device__ float  g_MM  [HIDD*HIDD];
__device__ float  g_a2  [Cc];
__device__ float  g_c2  [Cc];
__device__ float  g_wT1 [Cc*128];
__device__ float  g_w2T [HIDD*Cc];
__device__ unsigned int g_cnt;

// ---------------- K0a: pack xyz + zero accumulators ----------------
__global__ void pack_zero_kernel(const float* __restrict__ xyz) {
    int i = blockIdx.x*256 + threadIdx.x;
    if (i == 0) g_cnt = 0u;
    if (i < HIDD) { g_sum[i] = 0.f; g_sumsq[i] = 0.f; g_mv[i] = 0.f; }
    if (i < HIDD*HIDD) g_MM[i] = 0.f;
    if (i < ROWS) {
        float x = xyz[i*3+0], y = xyz[i*3+1], z = xyz[i*3+2];
        g_xyz4[i] = make_float4(x, y, z, x*x + y*y + z*z);
    }
}

// ---------------- K0b: weight prep ----------------
__global__ void wprep_kernel(const float* __restrict__ w1, const float* __restrict__ w2) {
    int i = blockIdx.x*256 + threadIdx.x;
    if (i < Cc*128) {
        int c = i >> 7, j = i & 127;
        float v;
        if (j < 64) v = w1[j*(2*Cc) + c];
        else { int d = j - 64; v = w1[d*(2*Cc) + Cc + c] - w1[d*(2*Cc) + c]; }
        g_wT1[i] = v;
    } else {
        int t = i - Cc*128;
        if (t < HIDD*Cc) {
            int d = t >> 9, e = t & 511;
            g_w2T[t] = w2[e*HIDD + d];
        }
    }
}

// ---------------- K1: KNN ----------------
__device__ __forceinline__ void insert_cand(float& dist, int& idx, float& thr,
                                            float dn, int in, int lane) {
    int pos = __popc(__ballot_sync(FULLM, dist <= dn));
    float sd = __shfl_up_sync(FULLM, dist, 1);
    int   si = __shfl_up_sync(FULLM, idx, 1);
    if (lane == pos)      { dist = dn; idx = in; }
    else if (lane > pos)  { dist = sd; idx = si; }
    thr = __shfl_sync(FULLM, dist, Kk - 1);
}

#define KTILE 1024
__global__ void __launch_bounds__(256) knn_kernel() {
    __shared__ float4 sa[KTILE/2];   // (x0,x1,y0,y1) per pair
    __shared__ float4 sb[KTILE/2];   // (z0,z1,w0,w1) per pair
    const int lane = threadIdx.x & 31;
    const int warp = threadIdx.x >> 5;
    const int qrow = blockIdx.x * 8 + warp;
    const int b = qrow >> 12;
    const float4* xb4 = g_xyz4 + (b << 12);
    const float4 qv = g_xyz4[qrow];
    const ull qx2 = pk2(qv.x, qv.x), qy2 = pk2(qv.y, qv.y);
    const ull qz2 = pk2(qv.z, qv.z), qw2 = pk2(qv.w, qv.w);
    const ull m2  = pk2(-2.0f, -2.0f);
    const float INF = __int_as_float(0x7f800000);

    float dist; int idx;
    {
        float4 c = xb4[lane];
        float dot = fmaf(qv.x, c.x, fmaf(qv.y, c.y, qv.z * c.z));
        dist = fmaf(-2.0f, dot, qv.w + c.w);
        idx = lane;
#pragma unroll
        for (int k = 2; k <= 32; k <<= 1) {
#pragma unroll
            for (int j = k >> 1; j > 0; j >>= 1) {
                float od = __shfl_xor_sync(FULLM, dist, j);
                int   oi = __shfl_xor_sync(FULLM, idx,  j);
                bool lowLane   = (lane & j) == 0;
                bool asc       = (lane & k) == 0;
                bool keepSmall = (lowLane == asc);
                bool otherSmall = (od < dist) | ((od == dist) & (oi < idx));
                if (otherSmall == keepSmall) { dist = od; idx = oi; }
            }
        }
    }
    float thr = __shfl_sync(FULLM, dist, Kk - 1);

    for (int t0 = 0; t0 < Nn; t0 += KTILE) {
        __syncthreads();
        for (int j = threadIdx.x; j < KTILE/2; j += 256) {
            float4 c0 = xb4[t0 + 2*j], c1 = xb4[t0 + 2*j + 1];
            sa[j] = make_float4(c0.x, c1.x, c0.y, c1.y);
            sb[j] = make_float4(c0.z, c1.z, c0.w, c1.w);
        }
        __syncthreads();
        const bool firstTile = (t0 == 0);
#pragma unroll 2
        for (int pb = 0; pb < KTILE/2; pb += 32) {
            float4 A  = sa[pb + lane];
            float4 Bv = sb[pb + lane];
            ull cx2 = pk2(A.x, A.y), cy2 = pk2(A.z, A.w);
            ull cz2 = pk2(Bv.x, Bv.y), cw2 = pk2(Bv.z, Bv.w);
            ull dot2 = fma2g(qx2, cx2, fma2g(qy2, cy2, mul2(qz2, cz2)));
            ull d2 = fma2g(m2, dot2, add2(qw2, cw2));
            float2 dd = up2(d2);
            if (firstTile && pb == 0 && lane < 16) { dd.x = INF; dd.y = INF; }
            unsigned m = __ballot_sync(FULLM, (dd.x < thr) | (dd.y < thr));
            while (m) {
                int src = __ffs(m) - 1; m &= m - 1;
                float d0 = __shfl_sync(FULLM, dd.x, src);
                float d1 = __shfl_sync(FULLM, dd.y, src);
                int ibase = t0 + (pb + src) * 2;
                if (d0 < thr) insert_cand(dist, idx, thr, d0, ibase,     lane);
                if (d1 < thr) insert_cand(dist, idx, thr, d1, ibase + 1, lane);
            }
        }
    }
    if (lane < Kk) g_idx[qrow*Kk + lane] = idx;
}

// ---------------- K2: SGEMM [16384x512]x[512x128] -> p|q ----------------
// 128x128 tile, 256 threads, TM=TN=8, KT=16 register-prefetch ping-pong (R10 proven config)
__global__ void __launch_bounds__(256) gemm_pq_kernel(const float* __restrict__ X) {
    __shared__ float As[2][16*132];
    __shared__ float Bs[2][16*136];
    const int tid = threadIdx.x;
    const int r0 = blockIdx.x * 128;
    const int ty = tid >> 4;            // 0..15
    const int tx = tid & 15;            // 0..15
    ull acc[8][4];
#pragma unroll
    for (int i = 0; i < 8; ++i)
#pragma unroll
        for (int j = 0; j < 4; ++j) acc[i][j] = 0ull;

    const int aRow = tid >> 1;          // 0..127
    const int aCol = (tid & 1) << 3;    // 0 or 8
    const int bRow = tid >> 4;          // 0..15
    const int bCol = (tid & 15) << 3;   // 0..120
    const float* aPtr = &X[(r0 + aRow)*Cc + aCol];
    const float* bPtr = &g_wT1[bRow*128 + bCol];

    float4 ra0 = *(const float4*)(aPtr);
    float4 ra1 = *(const float4*)(aPtr + 4);
    float4 rb0 = *(const float4*)(bPtr);
    float4 rb1 = *(const float4*)(bPtr + 4);
    {
        float* as = As[0];
        as[(aCol+0)*132+aRow]=ra0.x; as[(aCol+1)*132+aRow]=ra0.y;
        as[(aCol+2)*132+aRow]=ra0.z; as[(aCol+3)*132+aRow]=ra0.w;
        as[(aCol+4)*132+aRow]=ra1.x; as[(aCol+5)*132+aRow]=ra1.y;
        as[(aCol+6)*132+aRow]=ra1.z; as[(aCol+7)*132+aRow]=ra1.w;
        float4* bsv = (float4*)&Bs[0][bRow*136 + bCol];
        bsv[0] = rb0; bsv[1] = rb1;
    }
    __syncthreads();

    int buf = 0;
    for (int kt = 0; kt < Cc; kt += 16) {
        const bool more = (kt + 16) < Cc;
        if (more) {
            ra0 = *(const float4*)(aPtr + kt + 16);
            ra1 = *(const float4*)(aPtr + kt + 20);
            rb0 = *(const float4*)(bPtr + (kt+16)*128);
            rb1 = *(const float4*)(bPtr + (kt+16)*128 + 4);
        }
        const float* as = As[buf];
        const float* bs = Bs[buf];
#pragma unroll
        for (int kk = 0; kk < 16; ++kk) {
            float4 av0 = *(const float4*)&as[kk*132 + ty*8];
            float4 av1 = *(const float4*)&as[kk*132 + ty*8 + 4];
            float4 bv0 = *(const float4*)&bs[kk*136 + tx*8];
            float4 bv1 = *(const float4*)&bs[kk*136 + tx*8 + 4];
            ull b0 = pk2(bv0.x, bv0.y), b1 = pk2(bv0.z, bv0.w);
            ull b2p = pk2(bv1.x, bv1.y), b3 = pk2(bv1.z, bv1.w);
            float rav[8] = {av0.x,av0.y,av0.z,av0.w,av1.x,av1.y,av1.z,av1.w};
#pragma unroll
            for (int i = 0; i < 8; ++i) {
                ull ap = pk2(rav[i], rav[i]);
                fma2(acc[i][0], ap, b0);  fma2(acc[i][1], ap, b1);
                fma2(acc[i][2], ap, b2p); fma2(acc[i][3], ap, b3);
            }
        }
        if (more) {
            float* asn = As[buf^1];
            asn[(aCol+0)*132+aRow]=ra0.x; asn[(aCol+1)*132+aRow]=ra0.y;
            asn[(aCol+2)*132+aRow]=ra0.z; asn[(aCol+3)*132+aRow]=ra0.w;
            asn[(aCol+4)*132+aRow]=ra1.x; asn[(aCol+5)*132+aRow]=ra1.y;
            asn[(aCol+6)*132+aRow]=ra1.z; asn[(aCol+7)*132+aRow]=ra1.w;
            float4* bsn = (float4*)&Bs[buf^1][bRow*136 + bCol];
            bsn[0] = rb0; bsn[1] = rb1;
            __syncthreads();
        }
        buf ^= 1;
    }
#pragma unroll
    for (int i = 0; i < 8; ++i) {
        int row = r0 + ty*8 + i;
        float2 v0 = up2(acc[i][0]), v1 = up2(acc[i][1]);
        float2 v2 = up2(acc[i][2]), v3 = up2(acc[i][3]);
        float4 lo = make_float4(v0.x, v0.y, v1.x, v1.y);
        float4 hi = make_float4(v2.x, v2.y, v3.x, v3.y);
        if (tx < 8) {
            float4* dst = (float4*)&g_p[row*64 + tx*8];
            dst[0] = lo; dst[1] = hi;
        } else {
            float4* dst = (float4*)&g_q[row*64 + (tx-8)*8];
            dst[0] = lo; dst[1] = hi;
        }
    }
}

// ---------------- K3: gather (MLP=20 preload) + max/min + stats + last-block finalize1 ----------------
#define GATHER_GRID (ROWS/4)
__global__ void __launch_bounds__(256) gather_stats_kernel(const float* __restrict__ g1,
                                                           const float* __restrict__ b1) {
    __shared__ int sidx[4][Kk];
    __shared__ float rs[256], rs2[256];
    __shared__ bool isLast;
    const int tid = threadIdx.x;
    const int w = tid >> 6;
    const int d = tid & 63;
    const int r = blockIdx.x*4 + w;
    if (d < Kk) sidx[w][d] = g_idx[r*Kk + d];
    __syncthreads();
    const int b = r >> 12;
    const float* pb = g_p + (b << 12)*HIDD;
    const float qvv = g_q[r*HIDD + d];
    // phase 1: issue all 20 gathers (independent -> MLP=20 hides L2 latency)
    float pv[Kk];
#pragma unroll
    for (int k = 0; k < Kk; ++k) pv[k] = pb[sidx[w][k]*HIDD + d];
    // phase 2: reduce in same order as before (bitwise-identical sums)
    float mx = __int_as_float(0xff800000);
    float mn = __int_as_float(0x7f800000);
    float s = 0.f, s2 = 0.f;
#pragma unroll
    for (int k = 0; k < Kk; ++k) {
        float h = pv[k] + qvv;
        mx = fmaxf(mx, h); mn = fminf(mn, h);
        s += h; s2 = fmaf(h, h, s2);
    }
    g_hmax[r*HIDD + d] = mx;
    g_hmin[r*HIDD + d] = mn;
    rs[tid] = s; rs2[tid] = s2;
    __syncthreads();
    if (tid < 64) {
        float a  = rs[tid]  + rs[tid+64]  + rs[tid+128]  + rs[tid+192];
        float a2 = rs2[tid] + rs2[tid+64] + rs2[tid+128] + rs2[tid+192];
        atomicAdd(&g_sum[tid],   a);
        atomicAdd(&g_sumsq[tid], a2);
    }
    __threadfence();
    __syncthreads();
    if (tid == 0) {
        unsigned v = atomicInc(&g_cnt, 0xffffffffu);
        isLast = (v == GATHER_GRID - 1);
    }
    __syncthreads();
    if (isLast && tid < 64) {
        float su  = __ldcg(&g_sum[tid]);
        float sq  = __ldcg(&g_sumsq[tid]);
        float mu  = su * BNK_INV;
        float var = sq * BNK_INV - mu*mu;
        if (var < 0.f) var = 0.f;
        float a = g1[tid] * rsqrtf(var + EPSV);
        g_af[tid] = a;
        g_cf[tid] = b1[tid] - mu*a;
    }
}

// ---------------- K5: hn = lrelu(a*hsel + c), accumulate m and M (128 blocks) ----------------
__global__ void __launch_bounds__(256) hn_moments_kernel() {
    __shared__ float sh[64][68];
    __shared__ float sa[64], sc2[64];
    const int tid = threadIdx.x;
    if (tid < 64) { sa[tid] = g_af[tid]; sc2[tid] = g_cf[tid]; }
    const int du = (tid >> 4) << 2;
    const int dv = (tid & 15) << 2;
    float acc[4][4];
#pragma unroll
    for (int i = 0; i < 4; ++i)
#pragma unroll
        for (int j = 0; j < 4; ++j) acc[i][j] = 0.f;
    float msum = 0.f;

    for (int pass = 0; pass < 2; ++pass) {
        __syncthreads();
        const int r0 = blockIdx.x*128 + pass*64;
        for (int t = tid; t < 64*64; t += 256) {
            int rr = t >> 6, d = t & 63;
            float a = sa[d], c = sc2[d];
            float hv = (a >= 0.f) ? g_hmax[(r0+rr)*HIDD + d] : g_hmin[(r0+rr)*HIDD + d];
            float z = fmaf(a, hv, c);
            z = (z >= 0.f) ? z : SLOPE*z;
            sh[rr][d] = z;
            g_hn[(r0+rr)*HIDD + d] = z;
        }
        __syncthreads();
        if (tid < 64) {
            float s = 0.f;
#pragma unroll
            for (int rr = 0; rr < 64; ++rr) s += sh[rr][tid];
            msum += s;
        }
#pragma unroll 4
        for (int rr = 0; rr < 64; ++rr) {
            float4 u = *(const float4*)&sh[rr][du];
            float4 v = *(const float4*)&sh[rr][dv];
            float uu[4] = {u.x,u.y,u.z,u.w};
            float vv[4] = {v.x,v.y,v.z,v.w};
#pragma unroll
            for (int i = 0; i < 4; ++i)
#pragma unroll
                for (int j = 0; j < 4; ++j) acc[i][j] = fmaf(uu[i], vv[j], acc[i][j]);
        }
    }
    if (tid < 64) atomicAdd(&g_mv[tid], msum);
#pragma unroll
    for (int i = 0; i < 4; ++i)
#pragma unroll
        for (int j = 0; j < 4; ++j)
            atomicAdd(&g_MM[(du+i)*64 + dv+j], acc[i][j]);
}

// ---------------- K6: one warp per output channel e: v = w2_e*M, then a2/c2 ----------------
__global__ void __launch_bounds__(256) mmv_fin2_kernel(const float* __restrict__ w2,
                                                       const float* __restrict__ g2,
                                                       const float* __restrict__ b2) {
    const int gwarp = (blockIdx.x*256 + threadIdx.x) >> 5;   // 0..511 = e
    const int lane = threadIdx.x & 31;
    const int e = gwarp;
    const float* w2e = w2 + e*64;
    float vv0 = 0.f, vv1 = 0.f;
#pragma unroll
    for (int d = 0; d < 64; ++d) {
        float w = w2e[d];
        vv0 = fmaf(w, g_MM[d*64 + lane],      vv0);
        vv1 = fmaf(w, g_MM[d*64 + lane + 32], vv1);
    }
    float wl0 = w2e[lane], wl1 = w2e[lane + 32];
    float ey = fmaf(wl0, vv0, wl1*vv1);
    float mu = fmaf(wl0, g_mv[lane], wl1*g_mv[lane+32]);
#pragma unroll
    for (int off = 16; off > 0; off >>= 1) {
        ey += __shfl_down_sync(FULLM, ey, off);
        mu += __shfl_down_sync(FULLM, mu, off);
    }
    if (lane == 0) {
        mu *= BN_INV;
        ey *= BN_INV;
        float var = ey - mu*mu;
        if (var < 0.f) var = 0.f;
        float a = g2[e]*rsqrtf(var + EPSV);
        g_a2[e] = a;
        g_c2[e] = b2[e] - mu*a;
    }
}

// ---------------- K7: out = lrelu(a2 * (hn @ w2T) + c2), double-buffered ----------------
#define O_ASZ (16*132)
#define O_BSZ (16*136)
__global__ void __launch_bounds__(256) gemm_out_kernel(float* __restrict__ out) {
    __shared__ float As[2][O_ASZ];
    __shared__ float Bs[2][O_BSZ];
    const int tid = threadIdx.x;
    const int r0 = blockIdx.x * 128;
    const int e0 = blockIdx.y * 128;
    const int tx = tid & 15, ty = tid >> 4;
    ull acc[8][4];
#pragma unroll
    for (int i = 0; i < 8; ++i)
#pragma unroll
        for (int j = 0; j < 4; ++j) acc[i][j] = 0ull;

    const int aRow = tid >> 1;          // 0..127
    const int aCol = (tid & 1) << 3;    // 0 or 8
    const int bRow = tid >> 4;          // 0..15
    const int bCol = (tid & 15) << 3;   // 0..120
    const float* aPtr = &g_hn[(r0 + aRow)*HIDD + aCol];
    const float* bPtr = &g_w2T[bRow*Cc + e0 + bCol];

    float4 ra0 = *(const float4*)(aPtr);
    float4 ra1 = *(const float4*)(aPtr + 4);
    float4 rb0 = *(const float4*)(bPtr);
    float4 rb1 = *(const float4*)(bPtr + 4);
    {
        float* as = As[0];
        as[(aCol+0)*132+aRow]=ra0.x; as[(aCol+1)*132+aRow]=ra0.y;
        as[(aCol+2)*132+aRow]=ra0.z; as[(aCol+3)*132+aRow]=ra0.w;
        as[(aCol+4)*132+aRow]=ra1.x; as[(aCol+5)*132+aRow]=ra1.y;
        as[(aCol+6)*132+aRow]=ra1.z; as[(aCol+7)*132+aRow]=ra1.w;
        float4* bsv = (float4*)&Bs[0][bRow*136 + bCol];
        bsv[0] = rb0; bsv[1] = rb1;
    }
    __syncthreads();

    int buf = 0;
    for (int kt = 0; kt < HIDD; kt += 16) {
        const bool more = (kt + 16) < HIDD;
        if (more) {
            ra0 = *(const float4*)(aPtr + kt + 16);
            ra1 = *(const float4*)(aPtr + kt + 20);
            rb0 = *(const float4*)(bPtr + (kt+16)*Cc);
            rb1 = *(const float4*)(bPtr + (kt+16)*Cc + 4);
        }
        const float* as = As[buf];
        const float* bs = Bs[buf];
#pragma unroll
        for (int kk = 0; kk < 16; ++kk) {
            float4 av0 = *(const float4*)&as[kk*132 + ty*8];
            float4 av1 = *(const float4*)&as[kk*132 + ty*8 + 4];
            float4 bv0 = *(const float4*)&bs[kk*136 + tx*8];
            float4 bv1 = *(const float4*)&bs[kk*136 + tx*8 + 4];
            ull b0 = pk2(bv0.x, bv0.y), b1 = pk2(bv0.z, bv0.w);
            ull b2p = pk2(bv1.x, bv1.y), b3 = pk2(bv1.z, bv1.w);
            float rav[8] = {av0.x,av0.y,av0.z,av0.w,av1.x,av1.y,av1.z,av1.w};
#pragma unroll
            for (int i = 0; i < 8; ++i) {
                ull ap = pk2(rav[i], rav[i]);
                fma2(acc[i][0], ap, b0); fma2(acc[i][1], ap, b1);
                fma2(acc[i][2], ap, b2p); fma2(acc[i][3], ap, b3);
            }
        }
        if (more) {
            float* asn = As[buf^1];
            asn[(aCol+0)*132+aRow]=ra0.x; asn[(aCol+1)*132+aRow]=ra0.y;
            asn[(aCol+2)*132+aRow]=ra0.z; asn[(aCol+3)*132+aRow]=ra0.w;
            asn[(aCol+4)*132+aRow]=ra1.x; asn[(aCol+5)*132+aRow]=ra1.y;
            asn[(aCol+6)*132+aRow]=ra1.z; asn[(aCol+7)*132+aRow]=ra1.w;
            float4* bsn = (float4*)&Bs[buf^1][bRow*136 + bCol];
            bsn[0] = rb0; bsn[1] = rb1;
            __syncthreads();
        }
        buf ^= 1;
    }
    float a2r[8], c2r[8];
#pragma unroll
    for (int j = 0; j < 8; ++j) {
        a2r[j] = g_a2[e0 + tx*8 + j];
        c2r[j] = g_c2[e0 + tx*8 + j];
    }
#pragma unroll
    for (int i = 0; i < 8; ++i) {
        int row = r0 + ty*8 + i;
        float av[8];
        float2 t0v = up2(acc[i][0]); av[0]=t0v.x; av[1]=t0v.y;
        float2 t1v = up2(acc[i][1]); av[2]=t1v.x; av[3]=t1v.y;
        float2 t2v = up2(acc[i][2]); av[4]=t2v.x; av[5]=t2v.y;
        float2 t3v = up2(acc[i][3]); av[6]=t3v.x; av[7]=t3v.y;
        float v[8];
#pragma unroll
        for (int j = 0; j < 8; ++j) {
            float z = fmaf(a2r[j], av[j], c2r[j]);
            v[j] = (z >= 0.f) ? z : SLOPE*z;
        }
        float4* dst = (float4*)&out[row*Cc + e0 + tx*8];
        dst[0] = make_float4(v[0], v[1], v[2], v[3]);
        dst[1] = make_float4(v[4], v[5], v[6], v[7]);
    }
}

// ---------------- stream/event singletons ----------------
struct SideStream {
    cudaStream_t s;
    cudaEvent_t  forkEv, joinEv;
    SideStream() {
        cudaStreamCreateWithFlags(&s, cudaStreamNonBlocking);
        cudaEventCreateWithFlags(&forkEv, cudaEventDisableTiming);
        cudaEventCreateWithFlags(&joinEv, cudaEventDisableTiming);
    }
};
static SideStream& side() { static SideStream ss; return ss; }

// ---------------- launch ----------------
extern "C" void kernel_launch(void* const* d_in, const int* in_sizes, int n_in,
                              void* d_out, int out_size) {
    const float* x   = (const float*)d_in[0];
    const float* xyz = (const float*)d_in[1];
    const float* w1  = (const float*)d_in[2];
    const float* g1  = (const float*)d_in[3];
    const float* b1  = (const float*)d_in[4];
    const float* w2  = (const float*)d_in[5];
    const float* g2  = (const float*)d_in[6];
    const float* b2  = (const float*)d_in[7];
    float* out = (float*)d_out;
    SideStream& ss = side();

    // stream 0: pack/zero -> fork
    pack_zero_kernel<<<64, 256>>>(xyz);
    cudaEventRecord(ss.forkEv, 0);
    cudaStreamWaitEvent(ss.s, ss.forkEv, 0);

    // side stream: KNN (ALU/issue-bound) || main stream: weights + GEMM (fma/smem-bound)
    knn_kernel<<<2048, 256, 0, ss.s>>>();
    cudaEventRecord(ss.joinEv, ss.s);

    wprep_kernel<<<384, 256>>>(w1, w2);
    gemm_pq_kernel<<<128, 256>>>(x);

    // join: gather needs both knn idx and p|q
    cudaStreamWaitEvent(0, ss.joinEv, 0);
    gather_stats_kernel<<<GATHER_GRID, 256>>>(g1, b1);
    hn_moments_kernel<<<128, 256>>>();
    mmv_fin2_kernel<<<64, 256>>>(w2, g2, b2);
    gemm_out_kernel<<<dim3(ROWS/128, Cc/128), 256>>>(out);
}

// round 13
// speedup vs baseline: 1.1143x; 1.0087x over previous
#include <cuda_runtime.h>

#define Bb   4
#define Nn   4096
#define Cc   512
#define Kk   20
#define HIDD 64
#define ROWS (Bb*Nn)          // 16384
#define BNK_INV (1.0f/327680.0f)
#define BN_INV  (1.0f/16384.0f)
#define EPSV 1e-5f
#define SLOPE 0.2f
#define FULLM 0xffffffffu

typedef unsigned long long ull;
__device__ __forceinline__ ull pk2(float lo, float hi) {
    ull r; asm("mov.b64 %0,{%1,%2};" : "=l"(r) : "f"(lo), "f"(hi)); return r;
}
__device__ __forceinline__ void fma2(ull& d, ull a, ull b) {
    asm("fma.rn.f32x2 %0, %1, %2, %0;" : "+l"(d) : "l"(a), "l"(b));
}
__device__ __forceinline__ ull fma2g(ull a, ull b, ull c) {
    ull r; asm("fma.rn.f32x2 %0, %1, %2, %3;" : "=l"(r) : "l"(a), "l"(b), "l"(c)); return r;
}
__device__ __forceinline__ ull mul2(ull a, ull b) {
    ull r; asm("mul.rn.f32x2 %0, %1, %2;" : "=l"(r) : "l"(a), "l"(b)); return r;
}
__device__ __forceinline__ ull add2(ull a, ull b) {
    ull r; asm("add.rn.f32x2 %0, %1, %2;" : "=l"(r) : "l"(a), "l"(b)); return r;
}
__device__ __forceinline__ float2 up2(ull v) {
    float lo, hi; asm("mov.b64 {%0,%1},%2;" : "=f"(lo), "=f"(hi) : "l"(v));
    return make_float2(lo, hi);
}

// ---------------- scratch ----------------
__device__ float  g_p   [ROWS*HIDD];
__device__ float  g_q   [ROWS*HIDD];
__device__ int    g_idx [ROWS*Kk];
__device__ float4 g_xyz4[ROWS];
__device__ float  g_hmax[ROWS*HIDD];
__device__ float  g_hmin[ROWS*HIDD];
__device__ float  g_hn  [ROWS*HIDD];
__device__ float  g_sum [HIDD];
__device__ float  g_sumsq[HIDD];
__device__ float  g_af  [HIDD];
__device__ float  g_cf  [HIDD];
__device__ float  g_mv  [HIDD];
__device__ float  g_MM  [HIDD*HIDD];
__device__ float  g_a2  [Cc];
__device__ float  g_c2  [Cc];
__device__ float  g_wT1 [Cc*128];
__device__ float  g_w2T [HIDD*Cc];
__device__ unsigned int g_cnt;

// ---------------- K0a: pack xyz + zero accumulators ----------------
__global__ void pack_zero_kernel(const float* __restrict__ xyz) {
    int i = blockIdx.x*256 + threadIdx.x;
    if (i == 0) g_cnt = 0u;
    if (i < HIDD) { g_sum[i] = 0.f; g_sumsq[i] = 0.f; g_mv[i] = 0.f; }
    if (i < HIDD*HIDD) g_MM[i] = 0.f;
    if (i < ROWS) {
        float x = xyz[i*3+0], y = xyz[i*3+1], z = xyz[i*3+2];
        g_xyz4[i] = make_float4(x, y, z, x*x + y*y + z*z);
    }
}

// ---------------- K0b: weight prep ----------------
__global__ void wprep_kernel(const float* __restrict__ w1, const float* __restrict__ w2) {
    int i = blockIdx.x*256 + threadIdx.x;
    if (i < Cc*128) {
        int c = i >> 7, j = i & 127;
        float v;
        if (j < 64) v = w1[j*(2*Cc) + c];
        else { int d = j - 64; v = w1[d*(2*Cc) + Cc + c] - w1[d*(2*Cc) + c]; }
        g_wT1[i] = v;
    } else {
        int t = i - Cc*128;
        if (t < HIDD*Cc) {
            int d = t >> 9, e = t & 511;
            g_w2T[t] = w2[e*HIDD + d];
        }
    }
}

// ---------------- K1: KNN ----------------
// insert WITHOUT thr refresh: stale-thr filtering is correctness-safe (pos>=32 writes nothing)
__device__ __forceinline__ void insert_cand_nt(float& dist, int& idx,
                                               float dn, int in, int lane) {
    int pos = __popc(__ballot_sync(FULLM, dist <= dn));
    float sd = __shfl_up_sync(FULLM, dist, 1);
    int   si = __shfl_up_sync(FULLM, idx, 1);
    if (lane == pos)      { dist = dn; idx = in; }
    else if (lane > pos)  { dist = sd; idx = si; }
}

#define KTILE 1024
__global__ void __launch_bounds__(256) knn_kernel() {
    __shared__ ulonglong2 sx[KTILE/2];   // (x0x1, y0y1) pre-packed f32x2
    __shared__ ulonglong2 sz[KTILE/2];   // (z0z1, w0w1) pre-packed f32x2
    const int lane = threadIdx.x & 31;
    const int warp = threadIdx.x >> 5;
    const int qrow = blockIdx.x * 8 + warp;
    const int b = qrow >> 12;
    const float4* xb4 = g_xyz4 + (b << 12);
    const float4 qv = g_xyz4[qrow];
    const ull qx2 = pk2(qv.x, qv.x), qy2 = pk2(qv.y, qv.y);
    const ull qz2 = pk2(qv.z, qv.z), qw2 = pk2(qv.w, qv.w);
    const ull m2  = pk2(-2.0f, -2.0f);
    const float INF = __int_as_float(0x7f800000);

    float dist; int idx;
    {
        float4 c = xb4[lane];
        float dot = fmaf(qv.x, c.x, fmaf(qv.y, c.y, qv.z * c.z));
        dist = fmaf(-2.0f, dot, qv.w + c.w);
        idx = lane;
#pragma unroll
        for (int k = 2; k <= 32; k <<= 1) {
#pragma unroll
            for (int j = k >> 1; j > 0; j >>= 1) {
                float od = __shfl_xor_sync(FULLM, dist, j);
                int   oi = __shfl_xor_sync(FULLM, idx,  j);
                bool lowLane   = (lane & j) == 0;
                bool asc       = (lane & k) == 0;
                bool keepSmall = (lowLane == asc);
                bool otherSmall = (od < dist) | ((od == dist) & (oi < idx));
                if (otherSmall == keepSmall) { dist = od; idx = oi; }
            }
        }
    }
    float thr = __shfl_sync(FULLM, dist, Kk - 1);

    for (int t0 = 0; t0 < Nn; t0 += KTILE) {
        __syncthreads();
        for (int j = threadIdx.x; j < KTILE/2; j += 256) {
            float4 c0 = xb4[t0 + 2*j], c1 = xb4[t0 + 2*j + 1];
            sx[j] = make_ulonglong2(pk2(c0.x, c1.x), pk2(c0.y, c1.y));
            sz[j] = make_ulonglong2(pk2(c0.z, c1.z), pk2(c0.w, c1.w));
        }
        __syncthreads();
        const bool firstTile = (t0 == 0);
#pragma unroll 2
        for (int pb = 0; pb < KTILE/2; pb += 32) {
            ulonglong2 A = sx[pb + lane];
            ulonglong2 Bv = sz[pb + lane];
            ull dot2 = fma2g(qx2, A.x, fma2g(qy2, A.y, mul2(qz2, Bv.x)));
            ull d2 = fma2g(m2, dot2, add2(qw2, Bv.y));
            float2 dd = up2(d2);
            if (firstTile && pb == 0 && lane < 16) { dd.x = INF; dd.y = INF; }
            unsigned m = __ballot_sync(FULLM, (dd.x < thr) | (dd.y < thr));
            if (m) {
                do {
                    int src = __ffs(m) - 1; m &= m - 1;
                    float d0 = __shfl_sync(FULLM, dd.x, src);
                    float d1 = __shfl_sync(FULLM, dd.y, src);
                    int ibase = t0 + (pb + src) * 2;
                    if (d0 < thr) insert_cand_nt(dist, idx, d0, ibase,     lane);
                    if (d1 < thr) insert_cand_nt(dist, idx, d1, ibase + 1, lane);
                } while (m);
                thr = __shfl_sync(FULLM, dist, Kk - 1);   // one refresh per batch
            }
        }
    }
    if (lane < Kk) g_idx[qrow*Kk + lane] = idx;
}

// ---------------- K2: SGEMM [16384x512]x[512x128] -> p|q ----------------
// 128x128 tile, 256 threads, TM=TN=8, KT=16 register-prefetch ping-pong
__global__ void __launch_bounds__(256) gemm_pq_kernel(const float* __restrict__ X) {
    __shared__ __align__(16) float As[2][16*132];
    __shared__ __align__(16) float Bs[2][16*136];
    const int tid = threadIdx.x;
    const int r0 = blockIdx.x * 128;
    const int ty = tid >> 4;            // 0..15
    const int tx = tid & 15;            // 0..15
    ull acc[8][4];
#pragma unroll
    for (int i = 0; i < 8; ++i)
#pragma unroll
        for (int j = 0; j < 4; ++j) acc[i][j] = 0ull;

    const int aRow = tid >> 1;          // 0..127
    const int aCol = (tid & 1) << 3;    // 0 or 8
    const int bRow = tid >> 4;          // 0..15
    const int bCol = (tid & 15) << 3;   // 0..120
    const float* aPtr = &X[(r0 + aRow)*Cc + aCol];
    const float* bPtr = &g_wT1[bRow*128 + bCol];

    float4 ra0 = *(const float4*)(aPtr);
    float4 ra1 = *(const float4*)(aPtr + 4);
    float4 rb0 = *(const float4*)(bPtr);
    float4 rb1 = *(const float4*)(bPtr + 4);
    {
        float* as = As[0];
        as[(aCol+0)*132+aRow]=ra0.x; as[(aCol+1)*132+aRow]=ra0.y;
        as[(aCol+2)*132+aRow]=ra0.z; as[(aCol+3)*132+aRow]=ra0.w;
        as[(aCol+4)*132+aRow]=ra1.x; as[(aCol+5)*132+aRow]=ra1.y;
        as[(aCol+6)*132+aRow]=ra1.z; as[(aCol+7)*132+aRow]=ra1.w;
        float4* bsv = (float4*)&Bs[0][bRow*136 + bCol];
        bsv[0] = rb0; bsv[1] = rb1;
    }
    __syncthreads();

    int buf = 0;
    for (int kt = 0; kt < Cc; kt += 16) {
        const bool more = (kt + 16) < Cc;
        if (more) {
            ra0 = *(const float4*)(aPtr + kt + 16);
            ra1 = *(const float4*)(aPtr + kt + 20);
            rb0 = *(const float4*)(bPtr + (kt+16)*128);
            rb1 = *(const float4*)(bPtr + (kt+16)*128 + 4);
        }
        const float* as = As[buf];
        const float* bs = Bs[buf];
#pragma unroll
        for (int kk = 0; kk < 16; ++kk) {
            float4 av0 = *(const float4*)&as[kk*132 + ty*8];
            float4 av1 = *(const float4*)&as[kk*132 + ty*8 + 4];
            ulonglong2 bp0 = *(const ulonglong2*)&bs[kk*136 + tx*8];
            ulonglong2 bp1 = *(const ulonglong2*)&bs[kk*136 + tx*8 + 4];
            ull b0 = bp0.x, b1 = bp0.y, b2p = bp1.x, b3 = bp1.y;
            float rav[8] = {av0.x,av0.y,av0.z,av0.w,av1.x,av1.y,av1.z,av1.w};
#pragma unroll
            for (int i = 0; i < 8; ++i) {
                ull ap = pk2(rav[i], rav[i]);
                fma2(acc[i][0], ap, b0);  fma2(acc[i][1], ap, b1);
                fma2(acc[i][2], ap, b2p); fma2(acc[i][3], ap, b3);
            }
        }
        if (more) {
            float* asn = As[buf^1];
            asn[(aCol+0)*132+aRow]=ra0.x; asn[(aCol+1)*132+aRow]=ra0.y;
            asn[(aCol+2)*132+aRow]=ra0.z; asn[(aCol+3)*132+aRow]=ra0.w;
            asn[(aCol+4)*132+aRow]=ra1.x; asn[(aCol+5)*132+aRow]=ra1.y;
            asn[(aCol+6)*132+aRow]=ra1.z; asn[(aCol+7)*132+aRow]=ra1.w;
            float4* bsn = (float4*)&Bs[buf^1][bRow*136 + bCol];
            bsn[0] = rb0; bsn[1] = rb1;
            __syncthreads();
        }
        buf ^= 1;
    }
#pragma unroll
    for (int i = 0; i < 8; ++i) {
        int row = r0 + ty*8 + i;
        float2 v0 = up2(acc[i][0]), v1 = up2(acc[i][1]);
        float2 v2 = up2(acc[i][2]), v3 = up2(acc[i][3]);
        float4 lo = make_float4(v0.x, v0.y, v1.x, v1.y);
        float4 hi = make_float4(v2.x, v2.y, v3.x, v3.y);
        if (tx < 8) {
            float4* dst = (float4*)&g_p[row*64 + tx*8];
            dst[0] = lo; dst[1] = hi;
        } else {
            float4* dst = (float4*)&g_q[row*64 + (tx-8)*8];
            dst[0] = lo; dst[1] = hi;
        }
    }
}

// ---------------- K3: gather (MLP=20 preload) + max/min + stats + last-block finalize1 ----------------
#define GATHER_GRID (ROWS/4)
__global__ void __launch_bounds__(256) gather_stats_kernel(const float* __restrict__ g1,
                                                           const float* __restrict__ b1) {
    __shared__ int sidx[4][Kk];
    __shared__ float rs[256], rs2[256];
    __shared__ bool isLast;
    const int tid = threadIdx.x;
    const int w = tid >> 6;
    const int d = tid & 63;
    const int r = blockIdx.x*4 + w;
    if (d < Kk) sidx[w][d] = g_idx[r*Kk + d];
    __syncthreads();
    const int b = r >> 12;
    const float* pb = g_p + (b << 12)*HIDD;
    const float qvv = g_q[r*HIDD + d];
    float pv[Kk];
#pragma unroll
    for (int k = 0; k < Kk; ++k) pv[k] = pb[sidx[w][k]*HIDD + d];
    float mx = __int_as_float(0xff800000);
    float mn = __int_as_float(0x7f800000);
    float s = 0.f, s2 = 0.f;
#pragma unroll
    for (int k = 0; k < Kk; ++k) {
        float h = pv[k] + qvv;
        mx = fmaxf(mx, h); mn = fminf(mn, h);
        s += h; s2 = fmaf(h, h, s2);
    }
    g_hmax[r*HIDD + d] = mx;
    g_hmin[r*HIDD + d] = mn;
    rs[tid] = s; rs2[tid] = s2;
    __syncthreads();
    if (tid < 64) {
        float a  = rs[tid]  + rs[tid+64]  + rs[tid+128]  + rs[tid+192];
        float a2 = rs2[tid] + rs2[tid+64] + rs2[tid+128] + rs2[tid+192];
        atomicAdd(&g_sum[tid],   a);
        atomicAdd(&g_sumsq[tid], a2);
    }
    __threadfence();
    __syncthreads();
    if (tid == 0) {
        unsigned v = atomicInc(&g_cnt, 0xffffffffu);
        isLast = (v == GATHER_GRID - 1);
    }
    __syncthreads();
    if (isLast && tid < 64) {
        float su  = __ldcg(&g_sum[tid]);
        float sq  = __ldcg(&g_sumsq[tid]);
        float mu  = su * BNK_INV;
        float var = sq * BNK_INV - mu*mu;
        if (var < 0.f) var = 0.f;
        float a = g1[tid] * rsqrtf(var + EPSV);
        g_af[tid] = a;
        g_cf[tid] = b1[tid] - mu*a;
    }
}

// ---------------- K5: hn = lrelu(a*hsel + c), accumulate m and M (128 blocks) ----------------
__global__ void __launch_bounds__(256) hn_moments_kernel() {
    __shared__ float sh[64][68];
    __shared__ float sa[64], sc2[64];
    const int tid = threadIdx.x;
    if (tid < 64) { sa[tid] = g_af[tid]; sc2[tid] = g_cf[tid]; }
    const int du = (tid >> 4) << 2;
    const int dv = (tid & 15) << 2;
    float acc[4][4];
#pragma unroll
    for (int i = 0; i < 4; ++i)
#pragma unroll
        for (int j = 0; j < 4; ++j) acc[i][j] = 0.f;
    float msum = 0.f;

    for (int pass = 0; pass < 2; ++pass) {
        __syncthreads();
        const int r0 = blockIdx.x*128 + pass*64;
        for (int t = tid; t < 64*64; t += 256) {
            int rr = t >> 6, d = t & 63;
            float a = sa[d], c = sc2[d];
            float hv = (a >= 0.f) ? g_hmax[(r0+rr)*HIDD + d] : g_hmin[(r0+rr)*HIDD + d];
            float z = fmaf(a, hv, c);
            z = (z >= 0.f) ? z : SLOPE*z;
            sh[rr][d] = z;
            g_hn[(r0+rr)*HIDD + d] = z;
        }
        __syncthreads();
        if (tid < 64) {
            float s = 0.f;
#pragma unroll
            for (int rr = 0; rr < 64; ++rr) s += sh[rr][tid];
            msum += s;
        }
#pragma unroll 4
        for (int rr = 0; rr < 64; ++rr) {
            float4 u = *(const float4*)&sh[rr][du];
            float4 v = *(const float4*)&sh[rr][dv];
            float uu[4] = {u.x,u.y,u.z,u.w};
            float vv[4] = {v.x,v.y,v.z,v.w};
#pragma unroll
            for (int i = 0; i < 4; ++i)
#pragma unroll
                for (int j = 0; j < 4; ++j) acc[i][j] = fmaf(uu[i], vv[j], acc[i][j]);
        }
    }
    if (tid < 64) atomicAdd(&g_mv[tid], msum);
#pragma unroll
    for (int i = 0; i < 4; ++i)
#pragma unroll
        for (int j = 0; j < 4; ++j)
            atomicAdd(&g_MM[(du+i)*64 + dv+j], acc[i][j]);
}

// ---------------- K6: one warp per output channel e: v = w2_e*M, then a2/c2 ----------------
__global__ void __launch_bounds__(256) mmv_fin2_kernel(const float* __restrict__ w2,
                                                       const float* __restrict__ g2,
                                                       const float* __restrict__ b2) {
    const int gwarp = (blockIdx.x*256 + threadIdx.x) >> 5;   // 0..511 = e
    const int lane = threadIdx.x & 31;
    const int e = gwarp;
    const float* w2e = w2 + e*64;
    float vv0 = 0.f, vv1 = 0.f;
#pragma unroll
    for (int d = 0; d < 64; ++d) {
        float w = w2e[d];
        vv0 = fmaf(w, g_MM[d*64 + lane],      vv0);
        vv1 = fmaf(w, g_MM[d*64 + lane + 32], vv1);
    }
    float wl0 = w2e[lane], wl1 = w2e[lane + 32];
    float ey = fmaf(wl0, vv0, wl1*vv1);
    float mu = fmaf(wl0, g_mv[lane], wl1*g_mv[lane+32]);
#pragma unroll
    for (int off = 16; off > 0; off >>= 1) {
        ey += __shfl_down_sync(FULLM, ey, off);
        mu += __shfl_down_sync(FULLM, mu, off);
    }
    if (lane == 0) {
        mu *= BN_INV;
        ey *= BN_INV;
        float var = ey - mu*mu;
        if (var < 0.f) var = 0.f;
        float a = g2[e]*rsqrtf(var + EPSV);
        g_a2[e] = a;
        g_c2[e] = b2[e] - mu*a;
    }
}

// ---------------- K7: out = lrelu(a2 * (hn @ w2T) + c2), double-buffered ----------------
#define O_ASZ (16*132)
#define O_BSZ (16*136)
__global__ void __launch_bounds__(256) gemm_out_kernel(float* __restrict__ out) {
    __shared__ __align__(16) float As[2][O_ASZ];
    __shared__ __align__(16) float Bs[2][O_BSZ];
    const int tid = threadIdx.x;
    const int r0 = blockIdx.x * 128;
    const int e0 = blockIdx.y * 128;
    const int tx = tid & 15, ty = tid >> 4;
    ull acc[8][4];
#pragma unroll
    for (int i = 0; i < 8; ++i)
#pragma unroll
        for (int j = 0; j < 4; ++j) acc[i][j] = 0ull;

    const int aRow = tid >> 1;          // 0..127
    const int aCol = (tid & 1) << 3;    // 0 or 8
    const int bRow = tid >> 4;          // 0..15
    const int bCol = (tid & 15) << 3;   // 0..120
    const float* aPtr = &g_hn[(r0 + aRow)*HIDD + aCol];
    const float* bPtr = &g_w2T[bRow*Cc + e0 + bCol];

    float4 ra0 = *(const float4*)(aPtr);
    float4 ra1 = *(const float4*)(aPtr + 4);
    float4 rb0 = *(const float4*)(bPtr);
    float4 rb1 = *(const float4*)(bPtr + 4);
    {
        float* as = As[0];
        as[(aCol+0)*132+aRow]=ra0.x; as[(aCol+1)*132+aRow]=ra0.y;
        as[(aCol+2)*132+aRow]=ra0.z; as[(aCol+3)*132+aRow]=ra0.w;
        as[(aCol+4)*132+aRow]=ra1.x; as[(aCol+5)*132+aRow]=ra1.y;
        as[(aCol+6)*132+aRow]=ra1.z; as[(aCol+7)*132+aRow]=ra1.w;
        float4* bsv = (float4*)&Bs[0][bRow*136 + bCol];
        bsv[0] = rb0; bsv[1] = rb1;
    }
    __syncthreads();

    int buf = 0;
    for (int kt = 0; kt < HIDD; kt += 16) {
        const bool more = (kt + 16) < HIDD;
        if (more) {
            ra0 = *(const float4*)(aPtr + kt + 16);
            ra1 = *(const float4*)(aPtr + kt + 20);
            rb0 = *(const float4*)(bPtr + (kt+16)*Cc);
            rb1 = *(const float4*)(bPtr + (kt+16)*Cc + 4);
        }
        const float* as = As[buf];
        const float* bs = Bs[buf];
#pragma unroll
        for (int kk = 0; kk < 16; ++kk) {
            float4 av0 = *(const float4*)&as[kk*132 + ty*8];
            float4 av1 = *(const float4*)&as[kk*132 + ty*8 + 4];
            ulonglong2 bp0 = *(const ulonglong2*)&bs[kk*136 + tx*8];
            ulonglong2 bp1 = *(const ulonglong2*)&bs[kk*136 + tx*8 + 4];
            ull b0 = bp0.x, b1 = bp0.y, b2p = bp1.x, b3 = bp1.y;
            float rav[8] = {av0.x,av0.y,av0.z,av0.w,av1.x,av1.y,av1.z,av1.w};
#pragma unroll
            for (int i = 0; i < 8; ++i) {
                ull ap = pk2(rav[i], rav[i]);
                fma2(acc[i][0], ap, b0); fma2(acc[i][1], ap, b1);
                fma2(acc[i][2], ap, b2p); fma2(acc[i][3], ap, b3);
            }
        }
        if (more) {
            float* asn = As[buf^1];
            asn[(aCol+0)*132+aRow]=ra0.x; asn[(aCol+1)*132+aRow]=ra0.y;
            asn[(aCol+2)*132+aRow]=ra0.z; asn[(aCol+3)*132+aRow]=ra0.w;
            asn[(aCol+4)*132+aRow]=ra1.x; asn[(aCol+5)*132+aRow]=ra1.y;
            asn[(aCol+6)*132+aRow]=ra1.z; asn[(aCol+7)*132+aRow]=ra1.w;
            float4* bsn = (float4*)&Bs[buf^1][bRow*136 + bCol];
            bsn[0] = rb0; bsn[1] = rb1;
            __syncthreads();
        }
        buf ^= 1;
    }
    float a2r[8], c2r[8];
#pragma unroll
    for (int j = 0; j < 8; ++j) {
        a2r[j] = g_a2[e0 + tx*8 + j];
        c2r[j] = g_c2[e0 + tx*8 + j];
    }
#pragma unroll
    for (int i = 0; i < 8; ++i) {
        int row = r0 + ty*8 + i;
        float av[8];
        float2 t0v = up2(acc[i][0]); av[0]=t0v.x; av[1]=t0v.y;
        float2 t1v = up2(acc[i][1]); av[2]=t1v.x; av[3]=t1v.y;
        float2 t2v = up2(acc[i][2]); av[4]=t2v.x; av[5]=t2v.y;
        float2 t3v = up2(acc[i][3]); av[6]=t3v.x; av[7]=t3v.y;
        float v[8];
#pragma unroll
        for (int j = 0; j < 8; ++j) {
            float z = fmaf(a2r[j], av[j], c2r[j]);
            v[j] = (z >= 0.f) ? z : SLOPE*z;
        }
        float4* dst = (float4*)&out[row*Cc + e0 + tx*8];
        dst[0] = make_float4(v[0], v[1], v[2], v[3]);
        dst[1] = make_float4(v[4], v[5], v[6], v[7]);
    }
}

// ---------------- stream/event singletons ----------------
struct SideStream {
    cudaStream_t s;
    cudaEvent_t  forkEv, joinEv;
    SideStream() {
        cudaStreamCreateWithFlags(&s, cudaStreamNonBlocking);
        cudaEventCreateWithFlags(&forkEv, cudaEventDisableTiming);
        cudaEventCreateWithFlags(&joinEv, cudaEventDisableTiming);
    }
};
static SideStream& side() { static SideStream ss; return ss; }

// ---------------- launch ----------------
extern "C" void kernel_launch(void* const* d_in, const int* in_sizes, int n_in,
                              void* d_out, int out_size) {
    const float* x   = (const float*)d_in[0];
    const float* xyz = (const float*)d_in[1];
    const float* w1  = (const float*)d_in[2];
    const float* g1  = (const float*)d_in[3];
    const float* b1  = (const float*)d_in[4];
    const float* w2  = (const float*)d_in[5];
    const float* g2  = (const float*)d_in[6];
    const float* b2  = (const float*)d_in[7];
    float* out = (float*)d_out;
    SideStream& ss = side();

    // stream 0: pack/zero -> fork
    pack_zero_kernel<<<64, 256>>>(xyz);
    cudaEventRecord(ss.forkEv, 0);
    cudaStreamWaitEvent(ss.s, ss.forkEv, 0);

    // side stream: KNN (ALU/issue-bound) || main stream: weights + GEMM (fma/smem-bound)
    knn_kernel<<<2048, 256, 0, ss.s>>>();
    cudaEventRecord(ss.joinEv, ss.s);

    wprep_kernel<<<384, 256>>>(w1, w2);
    gemm_pq_kernel<<<128, 256>>>(x);

    // join: gather needs both knn idx and p|q
    cudaStreamWaitEvent(0, ss.joinEv, 0);
    gather_stats_kernel<<<GATHER_GRID, 256>>>(g1, b1);
    hn_moments_kernel<<<128, 256>>>();
    mmv_fin2_kernel<<<64, 256>>>(w2, g2, b2);
    gemm_out_kernel<<<dim3(ROWS/128, Cc/128), 256>>>(out);
}